// round 5
// baseline (speedup 1.0000x reference)
#include <cuda_runtime.h>
#include <cstdint>

#define BT 131072   // B*T = 256*512
#define TT 512

typedef unsigned long long ull;

// ---------------- scratch (device globals; no runtime allocation) ----------
__device__ float g_bufG[67108864];  // [BT,512]  G1 / G2 / Gd2 (reused)
__device__ float g_h1[16777216];    // [BT,128]
__device__ float g_d1[8388608];     // [BT,64]
__device__ float g_d2[16777216];    // [BT,128]
__device__ float g_z[16384];        // [256,64]
__device__ float g_gd1[65536];      // [256,256]

// ---------------- packed f32x2 helpers --------------------------------------
__device__ __forceinline__ ull dup2(float x) {
    ull r; asm("mov.b64 %0, {%1, %1};" : "=l"(r) : "f"(x)); return r;
}
__device__ __forceinline__ ull pack2(float lo, float hi) {
    ull r; asm("mov.b64 %0, {%1, %2};" : "=l"(r) : "f"(lo), "f"(hi)); return r;
}
__device__ __forceinline__ float2 unpack2(ull v) {
    float2 f; asm("mov.b64 {%0, %1}, %2;" : "=f"(f.x), "=f"(f.y) : "l"(v)); return f;
}
__device__ __forceinline__ void fma2(ull& acc, ull a, ull b) {
    asm("fma.rn.f32x2 %0, %1, %2, %0;" : "+l"(acc) : "l"(a), "l"(b));
}
__device__ __forceinline__ ull add2(ull a, ull b) {
    ull d; asm("add.rn.f32x2 %0, %1, %2;" : "=l"(d) : "l"(a), "l"(b)); return d;
}

// fast sigmoid: 1/(1 + 2^(-x*log2e)) via ex2.approx + rcp.approx (~1e-6 rel)
__device__ __forceinline__ float fsig(float x) {
    float r;
    asm("{\n\t.reg .f32 t;\n\t"
        "mul.f32 t, %1, 0fBFB8AA3B;\n\t"
        "ex2.approx.f32 t, t;\n\t"
        "add.f32 t, t, 0f3F800000;\n\t"
        "rcp.approx.f32 %0, t;\n\t}"
        : "=f"(r) : "f"(x));
    return r;
}

// ---------------- misc helpers ----------------------------------------------
__device__ __forceinline__ void cp_async16(void* smem_dst, const void* gmem_src) {
    uint32_t s = (uint32_t)__cvta_generic_to_shared(smem_dst);
    asm volatile("cp.async.cg.shared.global [%0], [%1], 16;\n" :: "r"(s), "l"(gmem_src));
}
__device__ __forceinline__ void cp_async_commit() { asm volatile("cp.async.commit_group;\n"); }
__device__ __forceinline__ void cp_async_wait6()  { asm volatile("cp.async.wait_group 6;\n"); }
__device__ __forceinline__ void cp_async_wait0()  { asm volatile("cp.async.wait_group 0;\n"); }

__device__ __forceinline__ void cluster_sync_() {
    asm volatile("barrier.cluster.arrive.aligned;\n" ::: "memory");
    asm volatile("barrier.cluster.wait.aligned;\n" ::: "memory");
}
__device__ __forceinline__ void st_remote_f32(float* local_ptr, uint32_t peer, float v) {
    uint32_t la = (uint32_t)__cvta_generic_to_shared(local_ptr);
    uint32_t ra;
    asm("mapa.shared::cluster.u32 %0, %1, %2;\n" : "=r"(ra) : "r"(la), "r"(peer));
    asm volatile("st.shared::cluster.f32 [%0], %1;\n" :: "r"(ra), "f"(v) : "memory");
}
__device__ __forceinline__ void mbar_arrive_remote(uint32_t local_mbar, uint32_t peer) {
    uint32_t ra;
    asm("mapa.shared::cluster.u32 %0, %1, %2;\n" : "=r"(ra) : "r"(local_mbar), "r"(peer));
    asm volatile("mbarrier.arrive.release.cluster.shared::cluster.b64 _, [%0];\n"
                 :: "r"(ra) : "memory");
}
__device__ __forceinline__ void mbar_wait(uint32_t mbar, uint32_t parity) {
    asm volatile(
        "{\n\t.reg .pred P;\n"
        "WAITL_%=:\n\t"
        "mbarrier.try_wait.parity.acquire.cluster.shared::cta.b64 P, [%0], %1, 0x989680;\n\t"
        "@!P bra WAITL_%=;\n"
        "}" :: "r"(mbar), "r"(parity) : "memory");
}

// ---------------- bulk GEMM: C[M,N] = A[M,K] @ W[K,N] + bias ----------------
// 128xBN tile, BK=16, 256 threads, f32x2 accumulation. (R3 proven version)
template<int BN>
__global__ void __launch_bounds__(256)
gemm_f32x2_kernel(const float* __restrict__ A,
                  const float* __restrict__ W,
                  const float* __restrict__ bias,
                  float* __restrict__ C,
                  int M, int N, int K) {
    __shared__ __align__(16) float As[2][16][128];
    __shared__ __align__(16) float Bs[2][16][BN];
    const int tid = threadIdx.x;
    const int m0 = blockIdx.x * 128, n0 = blockIdx.y * BN;
    const int tx = tid & 15, ty = tid >> 4;

    const int am = tid >> 1, ak = (tid & 1) * 8;
    const int NB_F4 = 16 * BN / 4;
    const int nper = NB_F4 / 256;

    ull acc[8][4];
#pragma unroll
    for (int i = 0; i < 8; i++)
#pragma unroll
        for (int j = 0; j < 4; j++) acc[i][j] = 0ull;

    const int nk = K / 16;

    {
        const float* ap = A + (size_t)(m0 + am) * K + ak;
        float4 va = *(const float4*)ap;
        float4 vb = *(const float4*)(ap + 4);
#pragma unroll
        for (int q = 0; q < nper; q++) {
            int idx = tid * nper + q;
            int br = idx / (BN / 4), bc = (idx % (BN / 4)) * 4;
            cp_async16(&Bs[0][br][bc], W + (size_t)br * N + n0 + bc);
        }
        cp_async_commit();
        As[0][ak + 0][am] = va.x; As[0][ak + 1][am] = va.y;
        As[0][ak + 2][am] = va.z; As[0][ak + 3][am] = va.w;
        As[0][ak + 4][am] = vb.x; As[0][ak + 5][am] = vb.y;
        As[0][ak + 6][am] = vb.z; As[0][ak + 7][am] = vb.w;
        cp_async_wait0();
        __syncthreads();
    }

    for (int kt = 0; kt < nk; kt++) {
        const int p = kt & 1;
        const bool more = (kt + 1) < nk;
        float4 va, vb;
        if (more) {
            const float* ap = A + (size_t)(m0 + am) * K + (kt + 1) * 16 + ak;
            va = *(const float4*)ap;
            vb = *(const float4*)(ap + 4);
#pragma unroll
            for (int q = 0; q < nper; q++) {
                int idx = tid * nper + q;
                int br = idx / (BN / 4), bc = (idx % (BN / 4)) * 4;
                cp_async16(&Bs[p ^ 1][br][bc], W + (size_t)((kt + 1) * 16 + br) * N + n0 + bc);
            }
        }
        cp_async_commit();

#pragma unroll
        for (int k = 0; k < 16; k++) {
            float4 a0 = *(const float4*)&As[p][k][ty * 4];
            float4 a1 = *(const float4*)&As[p][k][64 + ty * 4];
            ulonglong2 b0v = *(const ulonglong2*)&Bs[p][k][tx * 4];
            ulonglong2 b1v;
            if (BN == 128) b1v = *(const ulonglong2*)&Bs[p][k][64 + tx * 4];
            float av[8] = {a0.x, a0.y, a0.z, a0.w, a1.x, a1.y, a1.z, a1.w};
#pragma unroll
            for (int i = 0; i < 8; i++) {
                ull aa = dup2(av[i]);
                fma2(acc[i][0], aa, b0v.x);
                fma2(acc[i][1], aa, b0v.y);
                if (BN == 128) {
                    fma2(acc[i][2], aa, b1v.x);
                    fma2(acc[i][3], aa, b1v.y);
                }
            }
        }

        if (more) {
            As[p ^ 1][ak + 0][am] = va.x; As[p ^ 1][ak + 1][am] = va.y;
            As[p ^ 1][ak + 2][am] = va.z; As[p ^ 1][ak + 3][am] = va.w;
            As[p ^ 1][ak + 4][am] = vb.x; As[p ^ 1][ak + 5][am] = vb.y;
            As[p ^ 1][ak + 6][am] = vb.z; As[p ^ 1][ak + 7][am] = vb.w;
        }
        cp_async_wait0();
        __syncthreads();
    }

    ull bz[4];
    bz[0] = *(const ull*)&bias[n0 + tx * 4];
    bz[1] = *(const ull*)&bias[n0 + tx * 4 + 2];
    if (BN == 128) {
        bz[2] = *(const ull*)&bias[n0 + 64 + tx * 4];
        bz[3] = *(const ull*)&bias[n0 + 64 + tx * 4 + 2];
    }
#pragma unroll
    for (int i = 0; i < 8; i++) {
        int row = m0 + ((i < 4) ? (ty * 4 + i) : (64 + ty * 4 + i - 4));
        ulonglong2 o0;
        o0.x = add2(acc[i][0], bz[0]);
        o0.y = add2(acc[i][1], bz[1]);
        *(ulonglong2*)&C[(size_t)row * N + n0 + tx * 4] = o0;
        if (BN == 128) {
            ulonglong2 o1;
            o1.x = add2(acc[i][2], bz[2]);
            o1.y = add2(acc[i][3], bz[3]);
            *(ulonglong2*)&C[(size_t)row * N + n0 + 64 + tx * 4] = o1;
        }
    }
}

// ---------------- LSTM recurrence, H=64 (encoder L2 / decoder L1) -----------
// 128 CTAs x 512 threads, 2 batch rows per CTA.
// Thread = (row r, h-index j, k-quarter kh in 0..3). Computes all 4 gate
// partials over its 16-k quarter (weights as 32 u64 k-pairs in regs),
// combines quarters via 2-round shfl allreduce, applies gates inline.
// ONE barrier per step. 8-deep cp.async pipeline for gproj.
__global__ void __launch_bounds__(512)
lstm64_kernel(const float* __restrict__ gproj, // [BT,256] or [256,256] if constProj
              const float* __restrict__ Wr,    // [64,256]
              float* __restrict__ hseq,        // [BT,64] or null
              float* __restrict__ hlast,       // [256,64] or null
              int constProj) {
    __shared__ __align__(16) float h_s[2][2][64];
    __shared__ __align__(16) float gbuf[8][2][256];   // 16KB

    const int tid = threadIdx.x;
    const int b0 = blockIdx.x * 2;
    const int r = tid >> 8;             // row 0/1
    const int j = (tid >> 2) & 63;      // h-index
    const int kh = tid & 3;             // k quarter: k in [kh*16, kh*16+16)

    // weights: 4 gates x 8 k-pairs in this thread's quarter
    ull w2[32];
#pragma unroll
    for (int g = 0; g < 4; g++)
#pragma unroll
        for (int kp = 0; kp < 8; kp++) {
            int k = kh * 16 + 2 * kp;
            w2[g * 8 + kp] = pack2(Wr[k * 256 + g * 64 + j],
                                   Wr[(k + 1) * 256 + g * 64 + j]);
        }

    if (tid < 128) h_s[0][tid >> 6][tid & 63] = 0.f;

    const int pr = tid >> 6, c4 = (tid & 63) * 4;     // prefetch mapping (tid<128)
    float gc[4] = {0.f, 0.f, 0.f, 0.f};
    if (constProj) {
#pragma unroll
        for (int g = 0; g < 4; g++)
            gc[g] = gproj[(size_t)(b0 + r) * 256 + g * 64 + j];
    } else {
        for (int s = 0; s < 7; s++) {
            if (tid < 128)
                cp_async16(&gbuf[s][pr][c4], gproj + ((size_t)(b0 + pr) * TT + s) * 256 + c4);
            cp_async_commit();
        }
        cp_async_wait6();
    }
    __syncthreads();

    float c = 0.f;
    float hcur = 0.f;
    int p = 0;

    for (int t = 0; t < TT; t++) {
        const int st = t & 7;
        if (!constProj) {
            if (tid < 128 && t + 7 < TT)
                cp_async16(&gbuf[(t + 7) & 7][pr][c4],
                           gproj + ((size_t)(b0 + pr) * TT + t + 7) * 256 + c4);
            cp_async_commit();
        }

        // load this thread's 16-k quarter of h
        ull hv[8];
        const float* hp = &h_s[p][r][kh * 16];
#pragma unroll
        for (int qq = 0; qq < 4; qq++) {
            ulonglong2 v = *(const ulonglong2*)(hp + qq * 4);
            hv[qq * 2] = v.x; hv[qq * 2 + 1] = v.y;
        }

        // 4 gate partial dots over the quarter
        ull acc[4] = {0ull, 0ull, 0ull, 0ull};
#pragma unroll
        for (int kp = 0; kp < 8; kp++) {
#pragma unroll
            for (int g = 0; g < 4; g++)
                fma2(acc[g], w2[g * 8 + kp], hv[kp]);
        }
        float s[4];
#pragma unroll
        for (int g = 0; g < 4; g++) {
            float2 f = unpack2(acc[g]);
            s[g] = f.x + f.y;
            s[g] += __shfl_xor_sync(0xffffffffu, s[g], 1);
            s[g] += __shfl_xor_sync(0xffffffffu, s[g], 2);
        }

        float zi, zf, zg, zo;
        if (constProj) {
            zi = s[0] + gc[0]; zf = s[1] + gc[1]; zg = s[2] + gc[2]; zo = s[3] + gc[3];
        } else {
            zi = s[0] + gbuf[st][r][j];
            zf = s[1] + gbuf[st][r][64 + j];
            zg = s[2] + gbuf[st][r][128 + j];
            zo = s[3] + gbuf[st][r][192 + j];
        }
        c = fsig(zf) * c + fsig(zi) * fmaxf(zg, 0.f);
        hcur = fsig(zo) * fmaxf(c, 0.f);
        if (kh == 0) h_s[p ^ 1][r][j] = hcur;
        else if (kh == 1 && hseq) hseq[((size_t)(b0 + r) * TT + t) * 64 + j] = hcur;

        if (!constProj) cp_async_wait6();
        __syncthreads();
        p ^= 1;
    }
    if (hlast && kh == 0)
        hlast[(size_t)(b0 + r) * 64 + j] = hcur;
}

// ---------------- LSTM recurrence, H=128 (encoder L1 / decoder L2) ----------
// 2-CTA cluster, 64 clusters, 4 batch rows per CTA, 256 threads.
// Thread = (local h-index j in 0..63, k-quarter kh in 0..3). Computes all
// 4 gates x all 4 rows over its 32-k quarter (weights 64 u64 in regs), then a
// 2-round shfl reduce-scatter gives thread kh the full gate sums for row kh.
// Gates applied inline (no z smem). h pushed to peer via DSMEM, one
// release-arrive per warp on the peer's mbarrier (count=8).
__global__ void __launch_bounds__(256) __cluster_dims__(2, 1, 1)
lstm128_kernel(const float* __restrict__ gproj, // [BT,512]
               const float* __restrict__ Wr,    // [128,512]
               float* __restrict__ hseq) {      // [BT,128]
    __shared__ __align__(16) float h_s[2][4][128];    // 4KB
    __shared__ __align__(16) float gbuf[8][4][264];   // padded: conflict-free
    __shared__ __align__(8) ull mbar_s;

    const int tid = threadIdx.x;
    uint32_t q;
    asm("mov.u32 %0, %%cluster_ctarank;" : "=r"(q));
    const uint32_t peer = q ^ 1u;
    const int b0 = (blockIdx.x >> 1) * 4;
    const int j = (tid >> 2) & 63;
    const int kh = tid & 3;
    const int jg = (int)q * 64 + j;
    const int lane = tid & 31;

    // weights: 4 gates x 16 k-pairs in this thread's 32-k quarter
    ull w2[64];
#pragma unroll
    for (int g = 0; g < 4; g++)
#pragma unroll
        for (int kp = 0; kp < 16; kp++) {
            int k = kh * 32 + 2 * kp;
            int col = g * 128 + (int)q * 64 + j;
            w2[g * 16 + kp] = pack2(Wr[(size_t)k * 512 + col],
                                    Wr[(size_t)(k + 1) * 512 + col]);
        }

    for (int i = tid; i < 512; i += 256) h_s[0][i >> 7][i & 127] = 0.f;
    const uint32_t mbar = (uint32_t)__cvta_generic_to_shared(&mbar_s);
    if (tid == 0)
        asm volatile("mbarrier.init.shared.b64 [%0], %1;\n" :: "r"(mbar), "r"(8u) : "memory");
    __syncthreads();

    // prefetch mapping: 1 float4 per thread per stage
    const int pr = tid >> 6, c4 = (tid & 63) * 4;
    const int pcol = (c4 >> 6) * 128 + (int)q * 64 + (c4 & 63);
    for (int s = 0; s < 7; s++) {
        cp_async16(&gbuf[s][pr][c4], gproj + ((size_t)(b0 + pr) * TT + s) * 512 + pcol);
        cp_async_commit();
    }
    cp_async_wait6();
    __syncthreads();
    cluster_sync_();   // mbar + h buffers visible cluster-wide

    float c = 0.f;
    int p = 0;
    uint32_t par = 0;

    for (int t = 0; t < TT; t++) {
        const int st = t & 7;
        if (t + 7 < TT)
            cp_async16(&gbuf[(t + 7) & 7][pr][c4],
                       gproj + ((size_t)(b0 + pr) * TT + t + 7) * 512 + pcol);
        cp_async_commit();

        // phase 1: acc[g][r] partial dots over this thread's 32-k quarter
        ull acc[16];
#pragma unroll
        for (int i = 0; i < 16; i++) acc[i] = 0ull;
#pragma unroll
        for (int rr = 0; rr < 4; rr++) {
            ull hv[16];
            const float* hp = &h_s[p][rr][kh * 32];
#pragma unroll
            for (int qq = 0; qq < 8; qq++) {
                ulonglong2 v = *(const ulonglong2*)(hp + qq * 4);
                hv[qq * 2] = v.x; hv[qq * 2 + 1] = v.y;
            }
#pragma unroll
            for (int kp = 0; kp < 16; kp++) {
#pragma unroll
                for (int g = 0; g < 4; g++)
                    fma2(acc[g * 4 + rr], w2[g * 16 + kp], hv[kp]);
            }
        }

        // horizontal add + reduce-scatter over kh (thread kh ends with row kh)
        float s[16];
#pragma unroll
        for (int i = 0; i < 16; i++) {
            float2 f = unpack2(acc[i]);
            s[i] = f.x + f.y;
        }
        float zr[4];
        const bool hi2 = (kh & 2) != 0;
        const bool hi1 = (kh & 1) != 0;
#pragma unroll
        for (int g = 0; g < 4; g++) {
            float v0 = s[g * 4 + 0], v1 = s[g * 4 + 1];
            float v2 = s[g * 4 + 2], v3 = s[g * 4 + 3];
            float m0 = hi2 ? v2 : v0, m1 = hi2 ? v3 : v1;
            float o0 = hi2 ? v0 : v2, o1 = hi2 ? v1 : v3;
            m0 += __shfl_xor_sync(0xffffffffu, o0, 2);
            m1 += __shfl_xor_sync(0xffffffffu, o1, 2);
            float m = hi1 ? m1 : m0, o = hi1 ? m0 : m1;
            m += __shfl_xor_sync(0xffffffffu, o, 1);
            zr[g] = m;
        }

        // gates for (row kh, local col j)
        float zi = zr[0] + gbuf[st][kh][j];
        float zf = zr[1] + gbuf[st][kh][64 + j];
        float zg = zr[2] + gbuf[st][kh][128 + j];
        float zo = zr[3] + gbuf[st][kh][192 + j];
        c = fsig(zf) * c + fsig(zi) * fmaxf(zg, 0.f);
        float h = fsig(zo) * fmaxf(c, 0.f);
        float* own = &h_s[p ^ 1][kh][jg];
        *own = h;
        st_remote_f32(own, peer, h);
        hseq[((size_t)(b0 + kh) * TT + t) * 128 + jg] = h;
        __syncwarp();
        if (lane == 0) mbar_arrive_remote(mbar, peer);   // 1 release-arrive per warp

        cp_async_wait6();
        __syncthreads();       // local h half + gbuf ordering
        mbar_wait(mbar, par);  // acquire peer's 8 arrivals
        par ^= 1;
        p ^= 1;
    }
}

// ---------------- host orchestration ----------------------------------------
extern "C" void kernel_launch(void* const* d_in, const int* in_sizes, int n_in,
                              void* d_out, int out_size) {
    const float* x    = (const float*)d_in[0];
    const float* Wk1  = (const float*)d_in[1];
    const float* Wr1  = (const float*)d_in[2];
    const float* b1   = (const float*)d_in[3];
    const float* Wk2  = (const float*)d_in[4];
    const float* Wr2  = (const float*)d_in[5];
    const float* b2   = (const float*)d_in[6];
    const float* Wd1k = (const float*)d_in[7];
    const float* Wd1r = (const float*)d_in[8];
    const float* bd1  = (const float*)d_in[9];
    const float* Wd2k = (const float*)d_in[10];
    const float* Wd2r = (const float*)d_in[11];
    const float* bd2  = (const float*)d_in[12];
    const float* Wout = (const float*)d_in[13];
    const float* bout = (const float*)d_in[14];
    float* out = (float*)d_out;

    float *bufG, *h1, *d1, *d2, *z, *gd1;
    cudaGetSymbolAddress((void**)&bufG, g_bufG);
    cudaGetSymbolAddress((void**)&h1,  g_h1);
    cudaGetSymbolAddress((void**)&d1,  g_d1);
    cudaGetSymbolAddress((void**)&d2,  g_d2);
    cudaGetSymbolAddress((void**)&z,   g_z);
    cudaGetSymbolAddress((void**)&gd1, g_gd1);

    dim3 blk(256);
    dim3 blkL(512);

    // 1) G1 = x @ Wk1 + b1                     [BT,512]
    gemm_f32x2_kernel<128><<<dim3(1024, 4), blk>>>(x, Wk1, b1, bufG, BT, 512, 64);
    // 2) encoder L1 recurrence -> h1           [BT,128]
    lstm128_kernel<<<128, blk>>>(bufG, Wr1, h1);
    // 3) G2 = h1 @ Wk2 + b2                    [BT,256]
    gemm_f32x2_kernel<128><<<dim3(1024, 2), blk>>>(h1, Wk2, b2, bufG, BT, 256, 128);
    // 4) encoder L2 recurrence -> z (last h)   [256,64]
    lstm64_kernel<<<128, blkL>>>(bufG, Wr2, nullptr, z, 0);
    // 5) Gd1 = z @ Wd1k + bd1 (constant/step)  [256,256]
    gemm_f32x2_kernel<128><<<dim3(2, 2), blk>>>(z, Wd1k, bd1, gd1, 256, 256, 64);
    // 6) decoder L1 recurrence -> d1           [BT,64]
    lstm64_kernel<<<128, blkL>>>(gd1, Wd1r, d1, nullptr, 1);
    // 7) Gd2 = d1 @ Wd2k + bd2                 [BT,512]
    gemm_f32x2_kernel<128><<<dim3(1024, 4), blk>>>(d1, Wd2k, bd2, bufG, BT, 512, 64);
    // 8) decoder L2 recurrence -> d2           [BT,128]
    lstm128_kernel<<<128, blk>>>(bufG, Wd2r, d2);
    // 9) out = d2 @ Wout + bout                [BT,64] == [B,T,F]
    gemm_f32x2_kernel<64><<<dim3(1024, 1), blk>>>(d2, Wout, bout, out, BT, 64, 128);
}

// round 6
// speedup vs baseline: 1.3763x; 1.3763x over previous
#include <cuda_runtime.h>
#include <cstdint>

#define BT 131072   // B*T = 256*512
#define TT 512

typedef unsigned long long ull;

// ---------------- scratch (device globals; no runtime allocation) ----------
__device__ float g_bufG[67108864];  // [BT,512]  G1 / G2 / Gd2 (reused)
__device__ float g_h1[16777216];    // [BT,128]
__device__ float g_d1[8388608];     // [BT,64]
__device__ float g_d2[16777216];    // [BT,128]
__device__ float g_z[16384];        // [256,64]
__device__ float g_gd1[65536];      // [256,256]

// ---------------- packed f32x2 helpers --------------------------------------
__device__ __forceinline__ ull dup2(float x) {
    ull r; asm("mov.b64 %0, {%1, %1};" : "=l"(r) : "f"(x)); return r;
}
__device__ __forceinline__ ull pack2(float lo, float hi) {
    ull r; asm("mov.b64 %0, {%1, %2};" : "=l"(r) : "f"(lo), "f"(hi)); return r;
}
__device__ __forceinline__ float2 unpack2(ull v) {
    float2 f; asm("mov.b64 {%0, %1}, %2;" : "=f"(f.x), "=f"(f.y) : "l"(v)); return f;
}
__device__ __forceinline__ void fma2(ull& acc, ull a, ull b) {
    asm("fma.rn.f32x2 %0, %1, %2, %0;" : "+l"(acc) : "l"(a), "l"(b));
}
__device__ __forceinline__ ull add2(ull a, ull b) {
    ull d; asm("add.rn.f32x2 %0, %1, %2;" : "=l"(d) : "l"(a), "l"(b)); return d;
}

// fast sigmoid: 1/(1 + 2^(-x*log2e)) via ex2.approx + rcp.approx (~1e-6 rel)
__device__ __forceinline__ float fsig(float x) {
    float r;
    asm("{\n\t.reg .f32 t;\n\t"
        "mul.f32 t, %1, 0fBFB8AA3B;\n\t"
        "ex2.approx.f32 t, t;\n\t"
        "add.f32 t, t, 0f3F800000;\n\t"
        "rcp.approx.f32 %0, t;\n\t}"
        : "=f"(r) : "f"(x));
    return r;
}

// ---------------- misc helpers ----------------------------------------------
__device__ __forceinline__ void cp_async16(void* smem_dst, const void* gmem_src) {
    uint32_t s = (uint32_t)__cvta_generic_to_shared(smem_dst);
    asm volatile("cp.async.cg.shared.global [%0], [%1], 16;\n" :: "r"(s), "l"(gmem_src));
}
__device__ __forceinline__ void cp_async_commit() { asm volatile("cp.async.commit_group;\n"); }
__device__ __forceinline__ void cp_async_wait6()  { asm volatile("cp.async.wait_group 6;\n"); }
__device__ __forceinline__ void cp_async_wait0()  { asm volatile("cp.async.wait_group 0;\n"); }

__device__ __forceinline__ void cluster_sync_() {
    asm volatile("barrier.cluster.arrive.aligned;\n" ::: "memory");
    asm volatile("barrier.cluster.wait.aligned;\n" ::: "memory");
}
__device__ __forceinline__ void st_remote_f32(float* local_ptr, uint32_t peer, float v) {
    uint32_t la = (uint32_t)__cvta_generic_to_shared(local_ptr);
    uint32_t ra;
    asm("mapa.shared::cluster.u32 %0, %1, %2;\n" : "=r"(ra) : "r"(la), "r"(peer));
    asm volatile("st.shared::cluster.f32 [%0], %1;\n" :: "r"(ra), "f"(v) : "memory");
}
__device__ __forceinline__ void mbar_arrive_remote(uint32_t local_mbar, uint32_t peer) {
    uint32_t ra;
    asm("mapa.shared::cluster.u32 %0, %1, %2;\n" : "=r"(ra) : "r"(local_mbar), "r"(peer));
    asm volatile("mbarrier.arrive.release.cluster.shared::cluster.b64 _, [%0];\n"
                 :: "r"(ra) : "memory");
}
__device__ __forceinline__ void mbar_wait(uint32_t mbar, uint32_t parity) {
    asm volatile(
        "{\n\t.reg .pred P;\n"
        "WAITL_%=:\n\t"
        "mbarrier.try_wait.parity.acquire.cluster.shared::cta.b64 P, [%0], %1, 0x989680;\n\t"
        "@!P bra WAITL_%=;\n"
        "}" :: "r"(mbar), "r"(parity) : "memory");
}

// ---------------- bulk GEMM v5: C[M,N] = A[M,K] @ W[K,N] + bias -------------
// 512 threads, tile 128 x BN (BN=256 or 64), BK=32, per-thread 4 rows x BN/16
// cols, f32x2 accumulation, cp.async double-buffer for BOTH A and B.
// As stored [row][k] padded to stride 36 (conflict-free broadcast LDS.32).
// M%128==0, N%BN==0, K%32==0.
template<int BN>
__global__ void __launch_bounds__(512)
gemm5_kernel(const float* __restrict__ A,
             const float* __restrict__ W,
             const float* __restrict__ bias,
             float* __restrict__ C,
             int M, int N, int K) {
    constexpr int Q = BN / 64;              // col quads per thread
    extern __shared__ float sm[];
    float* As = sm;                          // [2][128][36]
    float* Bs = sm + 2 * 128 * 36;           // [2][32][BN]

    const int tid = threadIdx.x;
    const int m0 = blockIdx.x * 128, n0 = blockIdx.y * BN;
    const int ty = tid >> 4, tx = tid & 15;  // rows ty*4..+3, col quads tx*4+q*64

#define AS_(b, r, k) As[(b) * 4608 + (r) * 36 + (k)]
#define BS_(b, k, n) Bs[(b) * 32 * BN + (k) * BN + (n)]

    ull acc[4][2 * Q];
#pragma unroll
    for (int i = 0; i < 4; i++)
#pragma unroll
        for (int j = 0; j < 2 * Q; j++) acc[i][j] = 0ull;

    const int nk = K / 32;

    // tile 0
    {
#pragma unroll
        for (int q2 = 0; q2 < 2; q2++) {
            int idx = tid * 2 + q2;
            int r = idx >> 3, c4 = (idx & 7) * 4;
            cp_async16(&AS_(0, r, c4), A + (size_t)(m0 + r) * K + c4);
        }
#pragma unroll
        for (int q2 = 0; q2 < Q; q2++) {
            int idx = tid * Q + q2;
            int bk = idx / (BN / 4), bn = (idx % (BN / 4)) * 4;
            cp_async16(&BS_(0, bk, bn), W + (size_t)bk * N + n0 + bn);
        }
        cp_async_commit();
        cp_async_wait0();
        __syncthreads();
    }

    for (int kt = 0; kt < nk; kt++) {
        const int p = kt & 1;
        if (kt + 1 < nk) {
#pragma unroll
            for (int q2 = 0; q2 < 2; q2++) {
                int idx = tid * 2 + q2;
                int r = idx >> 3, c4 = (idx & 7) * 4;
                cp_async16(&AS_(p ^ 1, r, c4),
                           A + (size_t)(m0 + r) * K + (kt + 1) * 32 + c4);
            }
#pragma unroll
            for (int q2 = 0; q2 < Q; q2++) {
                int idx = tid * Q + q2;
                int bk = idx / (BN / 4), bn = (idx % (BN / 4)) * 4;
                cp_async16(&BS_(p ^ 1, bk, bn),
                           W + (size_t)((kt + 1) * 32 + bk) * N + n0 + bn);
            }
            cp_async_commit();
        }

#pragma unroll 4
        for (int k = 0; k < 32; k++) {
            ull ad[4];
#pragma unroll
            for (int i = 0; i < 4; i++)
                ad[i] = dup2(AS_(p, ty * 4 + i, k));
            ull bv[2 * Q];
#pragma unroll
            for (int q2 = 0; q2 < Q; q2++) {
                ulonglong2 b2 = *(const ulonglong2*)&BS_(p, k, tx * 4 + q2 * 64);
                bv[2 * q2] = b2.x; bv[2 * q2 + 1] = b2.y;
            }
#pragma unroll
            for (int i = 0; i < 4; i++)
#pragma unroll
                for (int j = 0; j < 2 * Q; j++)
                    fma2(acc[i][j], ad[i], bv[j]);
        }

        cp_async_wait0();
        __syncthreads();
    }

    // epilogue: bias + store
#pragma unroll
    for (int i = 0; i < 4; i++) {
        int row = m0 + ty * 4 + i;
#pragma unroll
        for (int q2 = 0; q2 < Q; q2++) {
            int col = n0 + tx * 4 + q2 * 64;
            float4 bb = *(const float4*)&bias[col];
            float2 f0 = unpack2(acc[i][2 * q2]);
            float2 f1 = unpack2(acc[i][2 * q2 + 1]);
            *(float4*)&C[(size_t)row * N + col] =
                make_float4(f0.x + bb.x, f0.y + bb.y, f1.x + bb.z, f1.y + bb.w);
        }
    }
#undef AS_
#undef BS_
}

// ---------------- LSTM recurrence, H=64 (R4 version; measured 263us) --------
// 128 CTAs x 256 threads, 2 batch rows per CTA.
// Thread = (row r, h-index j, k-half). Computes all 4 gate partials for (r,j)
// over its 32-k half (weights as 64 u64 k-pairs in regs), combines halves via
// shfl.bfly 16 (partner in-warp), applies gates locally. ONE barrier per step.
__global__ void __launch_bounds__(256)
lstm64_kernel(const float* __restrict__ gproj, // [BT,256] or [256,256] if constProj
              const float* __restrict__ Wr,    // [64,256]
              float* __restrict__ hseq,        // [BT,64] or null
              float* __restrict__ hlast,       // [256,64] or null
              int constProj) {
    __shared__ __align__(16) float h_s[2][2][64];
    __shared__ __align__(16) float gbuf[8][2][256];   // 16KB

    const int tid = threadIdx.x;
    const int b0 = blockIdx.x * 2;
    const int w = tid >> 5, lane = tid & 31;
    const int r = w >> 2;                    // row 0/1
    const int j = (w & 3) * 16 + (lane & 15);
    const int kh = lane >> 4;                // k half: k in [kh*32, kh*32+32)

    // weights: all 4 gates for column j, 16 k-pairs in this thread's half
    ull w2[64];
#pragma unroll
    for (int g = 0; g < 4; g++)
#pragma unroll
        for (int kp = 0; kp < 16; kp++) {
            int k = kh * 32 + 2 * kp;
            w2[g * 16 + kp] = pack2(Wr[k * 256 + g * 64 + j],
                                    Wr[(k + 1) * 256 + g * 64 + j]);
        }

    if (tid < 128) h_s[0][tid >> 6][tid & 63] = 0.f;

    const int pr = tid >> 6, c4 = (tid & 63) * 4;     // prefetch mapping (tid<128)
    float gc[4] = {0.f, 0.f, 0.f, 0.f};
    if (constProj) {
#pragma unroll
        for (int g = 0; g < 4; g++)
            gc[g] = gproj[(size_t)(b0 + r) * 256 + g * 64 + j];
    } else {
        for (int s = 0; s < 7; s++) {
            if (tid < 128)
                cp_async16(&gbuf[s][pr][c4], gproj + ((size_t)(b0 + pr) * TT + s) * 256 + c4);
            cp_async_commit();
        }
        cp_async_wait6();
    }
    __syncthreads();

    float c = 0.f;
    float hcur = 0.f;
    int p = 0;

    for (int t = 0; t < TT; t++) {
        const int st = t & 7;
        if (!constProj) {
            if (tid < 128 && t + 7 < TT)
                cp_async16(&gbuf[(t + 7) & 7][pr][c4],
                           gproj + ((size_t)(b0 + pr) * TT + t + 7) * 256 + c4);
            cp_async_commit();
        }

        // load this thread's 32-k half of h (broadcast LDS)
        ull hv[16];
        const float* hp = &h_s[p][r][kh * 32];
#pragma unroll
        for (int q = 0; q < 8; q++) {
            ulonglong2 v = *(const ulonglong2*)(hp + q * 4);
            hv[q * 2] = v.x; hv[q * 2 + 1] = v.y;
        }

        // 4 gate partial dots (even/odd kp chains for ILP)
        ull ae[4] = {0ull, 0ull, 0ull, 0ull};
        ull ao[4] = {0ull, 0ull, 0ull, 0ull};
#pragma unroll
        for (int kp = 0; kp < 16; kp += 2) {
#pragma unroll
            for (int g = 0; g < 4; g++) {
                fma2(ae[g], w2[g * 16 + kp], hv[kp]);
                fma2(ao[g], w2[g * 16 + kp + 1], hv[kp + 1]);
            }
        }
        float s[4];
#pragma unroll
        for (int g = 0; g < 4; g++) {
            float2 f = unpack2(add2(ae[g], ao[g]));
            s[g] = f.x + f.y;
            s[g] += __shfl_xor_sync(0xffffffffu, s[g], 16);
        }

        float zi, zf, zg, zo;
        if (constProj) {
            zi = s[0] + gc[0]; zf = s[1] + gc[1]; zg = s[2] + gc[2]; zo = s[3] + gc[3];
        } else {
            zi = s[0] + gbuf[st][r][j];
            zf = s[1] + gbuf[st][r][64 + j];
            zg = s[2] + gbuf[st][r][128 + j];
            zo = s[3] + gbuf[st][r][192 + j];
        }
        c = fsig(zf) * c + fsig(zi) * fmaxf(zg, 0.f);
        hcur = fsig(zo) * fmaxf(c, 0.f);
        if (kh == 0) h_s[p ^ 1][r][j] = hcur;
        else if (hseq) hseq[((size_t)(b0 + r) * TT + t) * 64 + j] = hcur;

        if (!constProj) cp_async_wait6();
        __syncthreads();
        p ^= 1;
    }
    if (hlast && kh == 0)
        hlast[(size_t)(b0 + r) * 64 + j] = hcur;
}

// ---------------- LSTM recurrence, H=128 (R3 version; known good) -----------
// 2-CTA cluster, 64 clusters, 4 batch rows per CTA. Each CTA owns 256 of the
// 512 gate columns; weights in registers as k-pairs (64 u64).
__global__ void __launch_bounds__(256) __cluster_dims__(2, 1, 1)
lstm128_kernel(const float* __restrict__ gproj, // [BT,512]
               const float* __restrict__ Wr,    // [128,512]
               float* __restrict__ hseq) {      // [BT,128]
    __shared__ __align__(16) float h_s[2][4][128];    // 4KB
    __shared__ __align__(16) float z_s[4][256];       // 4KB
    __shared__ __align__(16) float gbuf[8][4][256];   // 32KB
    __shared__ __align__(8) ull mbar_s;

    const int tid = threadIdx.x;
    uint32_t q;
    asm("mov.u32 %0, %%cluster_ctarank;" : "=r"(q));
    const uint32_t peer = q ^ 1u;
    const int b0 = (blockIdx.x >> 1) * 4;
    const int gcol = (tid >> 6) * 128 + (int)q * 64 + (tid & 63);

    ull w2[64];
#pragma unroll
    for (int kp = 0; kp < 64; kp++)
        w2[kp] = pack2(Wr[(size_t)(2 * kp) * 512 + gcol],
                       Wr[(size_t)(2 * kp + 1) * 512 + gcol]);

    for (int i = tid; i < 512; i += 256) h_s[0][i >> 7][i & 127] = 0.f;
    const uint32_t mbar = (uint32_t)__cvta_generic_to_shared(&mbar_s);
    if (tid == 0)
        asm volatile("mbarrier.init.shared.b64 [%0], %1;\n" :: "r"(mbar), "r"(8u) : "memory");
    __syncthreads();

    const int pr = tid >> 6, c4 = (tid & 63) * 4;
    const int pcol = (c4 >> 6) * 128 + (int)q * 64 + (c4 & 63);
    for (int s = 0; s < 7; s++) {
        cp_async16(&gbuf[s][pr][c4], gproj + ((size_t)(b0 + pr) * TT + s) * 512 + pcol);
        cp_async_commit();
    }
    cp_async_wait6();
    __syncthreads();
    cluster_sync_();

    const int r2 = tid >> 6, jj = tid & 63;
    const int jg = (int)q * 64 + jj;
    const int lane = tid & 31;
    float c = 0.f;
    int p = 0;
    uint32_t par = 0;

    for (int t = 0; t < TT; t++) {
        const int st = t & 7;
        if (t + 7 < TT)
            cp_async16(&gbuf[(t + 7) & 7][pr][c4],
                       gproj + ((size_t)(b0 + pr) * TT + t + 7) * 512 + pcol);
        cp_async_commit();

        ull a[4], e[4];
#pragma unroll
        for (int r = 0; r < 4; r++) { a[r] = 0ull; e[r] = 0ull; }
        const float* h0p = h_s[p][0];
        const float* h1p = h_s[p][1];
        const float* h2p = h_s[p][2];
        const float* h3p = h_s[p][3];
#pragma unroll
        for (int kp = 0; kp < 64; kp += 2) {
            ulonglong2 u0 = *(const ulonglong2*)(h0p + 2 * kp);
            ulonglong2 u1 = *(const ulonglong2*)(h1p + 2 * kp);
            ulonglong2 u2 = *(const ulonglong2*)(h2p + 2 * kp);
            ulonglong2 u3 = *(const ulonglong2*)(h3p + 2 * kp);
            fma2(a[0], w2[kp], u0.x); fma2(e[0], w2[kp + 1], u0.y);
            fma2(a[1], w2[kp], u1.x); fma2(e[1], w2[kp + 1], u1.y);
            fma2(a[2], w2[kp], u2.x); fma2(e[2], w2[kp + 1], u2.y);
            fma2(a[3], w2[kp], u3.x); fma2(e[3], w2[kp + 1], u3.y);
        }
#pragma unroll
        for (int r = 0; r < 4; r++) {
            float2 f = unpack2(add2(a[r], e[r]));
            z_s[r][tid] = gbuf[st][r][tid] + (f.x + f.y);
        }
        __syncthreads();

        {
            float zi = z_s[r2][jj];
            float zf = z_s[r2][64 + jj];
            float zg = z_s[r2][128 + jj];
            float zo = z_s[r2][192 + jj];
            c = fsig(zf) * c + fsig(zi) * fmaxf(zg, 0.f);
            float h = fsig(zo) * fmaxf(c, 0.f);
            float* own = &h_s[p ^ 1][r2][jg];
            *own = h;
            st_remote_f32(own, peer, h);
            hseq[((size_t)(b0 + r2) * TT + t) * 128 + jg] = h;
            __syncwarp();
            if (lane == 0) mbar_arrive_remote(mbar, peer);
        }
        cp_async_wait6();
        __syncthreads();
        mbar_wait(mbar, par);
        par ^= 1;
        p ^= 1;
    }
}

// ---------------- host orchestration ----------------------------------------
extern "C" void kernel_launch(void* const* d_in, const int* in_sizes, int n_in,
                              void* d_out, int out_size) {
    const float* x    = (const float*)d_in[0];
    const float* Wk1  = (const float*)d_in[1];
    const float* Wr1  = (const float*)d_in[2];
    const float* b1   = (const float*)d_in[3];
    const float* Wk2  = (const float*)d_in[4];
    const float* Wr2  = (const float*)d_in[5];
    const float* b2   = (const float*)d_in[6];
    const float* Wd1k = (const float*)d_in[7];
    const float* Wd1r = (const float*)d_in[8];
    const float* bd1  = (const float*)d_in[9];
    const float* Wd2k = (const float*)d_in[10];
    const float* Wd2r = (const float*)d_in[11];
    const float* bd2  = (const float*)d_in[12];
    const float* Wout = (const float*)d_in[13];
    const float* bout = (const float*)d_in[14];
    float* out = (float*)d_out;

    float *bufG, *h1, *d1, *d2, *z, *gd1;
    cudaGetSymbolAddress((void**)&bufG, g_bufG);
    cudaGetSymbolAddress((void**)&h1,  g_h1);
    cudaGetSymbolAddress((void**)&d1,  g_d1);
    cudaGetSymbolAddress((void**)&d2,  g_d2);
    cudaGetSymbolAddress((void**)&z,   g_z);
    cudaGetSymbolAddress((void**)&gd1, g_gd1);

    const int SMEM_G256 = (2 * 128 * 36 + 2 * 32 * 256) * 4;  // 102400
    const int SMEM_G64  = (2 * 128 * 36 + 2 * 32 * 64) * 4;   // 53248
    cudaFuncSetAttribute(gemm5_kernel<256>, cudaFuncAttributeMaxDynamicSharedMemorySize, SMEM_G256);
    cudaFuncSetAttribute(gemm5_kernel<64>,  cudaFuncAttributeMaxDynamicSharedMemorySize, SMEM_G64);

    dim3 blk(256);
    dim3 blkG(512);

    // 1) G1 = x @ Wk1 + b1                     [BT,512]
    gemm5_kernel<256><<<dim3(1024, 2), blkG, SMEM_G256>>>(x, Wk1, b1, bufG, BT, 512, 64);
    // 2) encoder L1 recurrence -> h1           [BT,128]
    lstm128_kernel<<<128, blk>>>(bufG, Wr1, h1);
    // 3) G2 = h1 @ Wk2 + b2                    [BT,256]
    gemm5_kernel<256><<<dim3(1024, 1), blkG, SMEM_G256>>>(h1, Wk2, b2, bufG, BT, 256, 128);
    // 4) encoder L2 recurrence -> z (last h)   [256,64]
    lstm64_kernel<<<128, blk>>>(bufG, Wr2, nullptr, z, 0);
    // 5) Gd1 = z @ Wd1k + bd1 (constant/step)  [256,256]
    gemm5_kernel<256><<<dim3(2, 1), blkG, SMEM_G256>>>(z, Wd1k, bd1, gd1, 256, 256, 64);
    // 6) decoder L1 recurrence -> d1           [BT,64]
    lstm64_kernel<<<128, blk>>>(gd1, Wd1r, d1, nullptr, 1);
    // 7) Gd2 = d1 @ Wd2k + bd2                 [BT,512]
    gemm5_kernel<256><<<dim3(1024, 2), blkG, SMEM_G256>>>(d1, Wd2k, bd2, bufG, BT, 512, 64);
    // 8) decoder L2 recurrence -> d2           [BT,128]
    lstm128_kernel<<<128, blk>>>(bufG, Wd2r, d2);
    // 9) out = d2 @ Wout + bout                [BT,64] == [B,T,F]
    gemm5_kernel<64><<<dim3(1024, 1), blkG, SMEM_G64>>>(d2, Wout, bout, out, BT, 64, 128);
}

// round 8
// speedup vs baseline: 1.4014x; 1.0182x over previous
#include <cuda_runtime.h>
#include <cstdint>

#define BT 131072   // B*T = 256*512
#define TT 512

typedef unsigned long long ull;

// ---------------- scratch (device globals; no runtime allocation) ----------
__device__ float g_bufG[67108864];  // [BT,512]  G1 / G2 / Gd2 (reused)
__device__ float g_h1[16777216];    // [BT,128]
__device__ float g_d1[8388608];     // [BT,64]
__device__ float g_z[16384];        // [256,64]
__device__ float g_gd1[65536];      // [256,256]

// ---------------- packed f32x2 helpers --------------------------------------
__device__ __forceinline__ ull dup2(float x) {
    ull r; asm("mov.b64 %0, {%1, %1};" : "=l"(r) : "f"(x)); return r;
}
__device__ __forceinline__ ull pack2(float lo, float hi) {
    ull r; asm("mov.b64 %0, {%1, %2};" : "=l"(r) : "f"(lo), "f"(hi)); return r;
}
__device__ __forceinline__ float2 unpack2(ull v) {
    float2 f; asm("mov.b64 {%0, %1}, %2;" : "=f"(f.x), "=f"(f.y) : "l"(v)); return f;
}
__device__ __forceinline__ void fma2(ull& acc, ull a, ull b) {
    asm("fma.rn.f32x2 %0, %1, %2, %0;" : "+l"(acc) : "l"(a), "l"(b));
}
__device__ __forceinline__ ull add2(ull a, ull b) {
    ull d; asm("add.rn.f32x2 %0, %1, %2;" : "=l"(d) : "l"(a), "l"(b)); return d;
}

// fast sigmoid: 1/(1 + 2^(-x*log2e)) via ex2.approx + rcp.approx (~1e-6 rel)
__device__ __forceinline__ float fsig(float x) {
    float r;
    asm("{\n\t.reg .f32 t;\n\t"
        "mul.f32 t, %1, 0fBFB8AA3B;\n\t"
        "ex2.approx.f32 t, t;\n\t"
        "add.f32 t, t, 0f3F800000;\n\t"
        "rcp.approx.f32 %0, t;\n\t}"
        : "=f"(r) : "f"(x));
    return r;
}

// ---------------- misc helpers ----------------------------------------------
__device__ __forceinline__ void cp_async16(void* smem_dst, const void* gmem_src) {
    uint32_t s = (uint32_t)__cvta_generic_to_shared(smem_dst);
    asm volatile("cp.async.cg.shared.global [%0], [%1], 16;\n" :: "r"(s), "l"(gmem_src));
}
__device__ __forceinline__ void cp_async_commit() { asm volatile("cp.async.commit_group;\n"); }
__device__ __forceinline__ void cp_async_wait6()  { asm volatile("cp.async.wait_group 6;\n"); }
__device__ __forceinline__ void cp_async_wait0()  { asm volatile("cp.async.wait_group 0;\n"); }

__device__ __forceinline__ void cluster_sync_() {
    asm volatile("barrier.cluster.arrive.aligned;\n" ::: "memory");
    asm volatile("barrier.cluster.wait.aligned;\n" ::: "memory");
}
__device__ __forceinline__ void st_remote_f32(float* local_ptr, uint32_t peer, float v) {
    uint32_t la = (uint32_t)__cvta_generic_to_shared(local_ptr);
    uint32_t ra;
    asm("mapa.shared::cluster.u32 %0, %1, %2;\n" : "=r"(ra) : "r"(la), "r"(peer));
    asm volatile("st.shared::cluster.f32 [%0], %1;\n" :: "r"(ra), "f"(v) : "memory");
}
__device__ __forceinline__ void mbar_arrive_remote(uint32_t local_mbar, uint32_t peer) {
    uint32_t ra;
    asm("mapa.shared::cluster.u32 %0, %1, %2;\n" : "=r"(ra) : "r"(local_mbar), "r"(peer));
    asm volatile("mbarrier.arrive.release.cluster.shared::cluster.b64 _, [%0];\n"
                 :: "r"(ra) : "memory");
}
__device__ __forceinline__ void mbar_wait(uint32_t mbar, uint32_t parity) {
    asm volatile(
        "{\n\t.reg .pred P;\n"
        "WAITL_%=:\n\t"
        "mbarrier.try_wait.parity.acquire.cluster.shared::cta.b64 P, [%0], %1, 0x989680;\n\t"
        "@!P bra WAITL_%=;\n"
        "}" :: "r"(mbar), "r"(parity) : "memory");
}

// ---------------- bulk GEMM: C[M,N] = A[M,K] @ W[K,N] + bias ----------------
// 128x128 tile, BK=16, 256 threads, f32x2 accumulation. (R3 proven version)
__global__ void __launch_bounds__(256)
gemm_f32x2_kernel(const float* __restrict__ A,
                  const float* __restrict__ W,
                  const float* __restrict__ bias,
                  float* __restrict__ C,
                  int M, int N, int K) {
    constexpr int BN = 128;
    __shared__ __align__(16) float As[2][16][128];
    __shared__ __align__(16) float Bs[2][16][BN];
    const int tid = threadIdx.x;
    const int m0 = blockIdx.x * 128, n0 = blockIdx.y * BN;
    const int tx = tid & 15, ty = tid >> 4;

    const int am = tid >> 1, ak = (tid & 1) * 8;
    const int nper = (16 * BN / 4) / 256;   // 2

    ull acc[8][4];
#pragma unroll
    for (int i = 0; i < 8; i++)
#pragma unroll
        for (int j = 0; j < 4; j++) acc[i][j] = 0ull;

    const int nk = K / 16;

    {
        const float* ap = A + (size_t)(m0 + am) * K + ak;
        float4 va = *(const float4*)ap;
        float4 vb = *(const float4*)(ap + 4);
#pragma unroll
        for (int q = 0; q < nper; q++) {
            int idx = tid * nper + q;
            int br = idx / (BN / 4), bc = (idx % (BN / 4)) * 4;
            cp_async16(&Bs[0][br][bc], W + (size_t)br * N + n0 + bc);
        }
        cp_async_commit();
        As[0][ak + 0][am] = va.x; As[0][ak + 1][am] = va.y;
        As[0][ak + 2][am] = va.z; As[0][ak + 3][am] = va.w;
        As[0][ak + 4][am] = vb.x; As[0][ak + 5][am] = vb.y;
        As[0][ak + 6][am] = vb.z; As[0][ak + 7][am] = vb.w;
        cp_async_wait0();
        __syncthreads();
    }

    for (int kt = 0; kt < nk; kt++) {
        const int p = kt & 1;
        const bool more = (kt + 1) < nk;
        float4 va, vb;
        if (more) {
            const float* ap = A + (size_t)(m0 + am) * K + (kt + 1) * 16 + ak;
            va = *(const float4*)ap;
            vb = *(const float4*)(ap + 4);
#pragma unroll
            for (int q = 0; q < nper; q++) {
                int idx = tid * nper + q;
                int br = idx / (BN / 4), bc = (idx % (BN / 4)) * 4;
                cp_async16(&Bs[p ^ 1][br][bc], W + (size_t)((kt + 1) * 16 + br) * N + n0 + bc);
            }
        }
        cp_async_commit();

#pragma unroll
        for (int k = 0; k < 16; k++) {
            float4 a0 = *(const float4*)&As[p][k][ty * 4];
            float4 a1 = *(const float4*)&As[p][k][64 + ty * 4];
            ulonglong2 b0v = *(const ulonglong2*)&Bs[p][k][tx * 4];
            ulonglong2 b1v = *(const ulonglong2*)&Bs[p][k][64 + tx * 4];
            float av[8] = {a0.x, a0.y, a0.z, a0.w, a1.x, a1.y, a1.z, a1.w};
#pragma unroll
            for (int i = 0; i < 8; i++) {
                ull aa = dup2(av[i]);
                fma2(acc[i][0], aa, b0v.x);
                fma2(acc[i][1], aa, b0v.y);
                fma2(acc[i][2], aa, b1v.x);
                fma2(acc[i][3], aa, b1v.y);
            }
        }

        if (more) {
            As[p ^ 1][ak + 0][am] = va.x; As[p ^ 1][ak + 1][am] = va.y;
            As[p ^ 1][ak + 2][am] = va.z; As[p ^ 1][ak + 3][am] = va.w;
            As[p ^ 1][ak + 4][am] = vb.x; As[p ^ 1][ak + 5][am] = vb.y;
            As[p ^ 1][ak + 6][am] = vb.z; As[p ^ 1][ak + 7][am] = vb.w;
        }
        cp_async_wait0();
        __syncthreads();
    }

    ull bz[4];
    bz[0] = *(const ull*)&bias[n0 + tx * 4];
    bz[1] = *(const ull*)&bias[n0 + tx * 4 + 2];
    bz[2] = *(const ull*)&bias[n0 + 64 + tx * 4];
    bz[3] = *(const ull*)&bias[n0 + 64 + tx * 4 + 2];
#pragma unroll
    for (int i = 0; i < 8; i++) {
        int row = m0 + ((i < 4) ? (ty * 4 + i) : (64 + ty * 4 + i - 4));
        ulonglong2 o0;
        o0.x = add2(acc[i][0], bz[0]);
        o0.y = add2(acc[i][1], bz[1]);
        *(ulonglong2*)&C[(size_t)row * N + n0 + tx * 4] = o0;
        ulonglong2 o1;
        o1.x = add2(acc[i][2], bz[2]);
        o1.y = add2(acc[i][3], bz[3]);
        *(ulonglong2*)&C[(size_t)row * N + n0 + 64 + tx * 4] = o1;
    }
}

// ---------------- LSTM recurrence, H=64 (R4 version; measured ~265us) -------
__global__ void __launch_bounds__(256)
lstm64_kernel(const float* __restrict__ gproj, // [BT,256] or [256,256] if constProj
              const float* __restrict__ Wr,    // [64,256]
              float* __restrict__ hseq,        // [BT,64] or null
              float* __restrict__ hlast,       // [256,64] or null
              int constProj) {
    __shared__ __align__(16) float h_s[2][2][64];
    __shared__ __align__(16) float gbuf[8][2][256];   // 16KB

    const int tid = threadIdx.x;
    const int b0 = blockIdx.x * 2;
    const int w = tid >> 5, lane = tid & 31;
    const int r = w >> 2;                    // row 0/1
    const int j = (w & 3) * 16 + (lane & 15);
    const int kh = lane >> 4;                // k half: k in [kh*32, kh*32+32)

    ull w2[64];
#pragma unroll
    for (int g = 0; g < 4; g++)
#pragma unroll
        for (int kp = 0; kp < 16; kp++) {
            int k = kh * 32 + 2 * kp;
            w2[g * 16 + kp] = pack2(Wr[k * 256 + g * 64 + j],
                                    Wr[(k + 1) * 256 + g * 64 + j]);
        }

    if (tid < 128) h_s[0][tid >> 6][tid & 63] = 0.f;

    const int pr = tid >> 6, c4 = (tid & 63) * 4;
    float gc[4] = {0.f, 0.f, 0.f, 0.f};
    if (constProj) {
#pragma unroll
        for (int g = 0; g < 4; g++)
            gc[g] = gproj[(size_t)(b0 + r) * 256 + g * 64 + j];
    } else {
        for (int s = 0; s < 7; s++) {
            if (tid < 128)
                cp_async16(&gbuf[s][pr][c4], gproj + ((size_t)(b0 + pr) * TT + s) * 256 + c4);
            cp_async_commit();
        }
        cp_async_wait6();
    }
    __syncthreads();

    float c = 0.f;
    float hcur = 0.f;
    int p = 0;

    for (int t = 0; t < TT; t++) {
        const int st = t & 7;
        if (!constProj) {
            if (tid < 128 && t + 7 < TT)
                cp_async16(&gbuf[(t + 7) & 7][pr][c4],
                           gproj + ((size_t)(b0 + pr) * TT + t + 7) * 256 + c4);
            cp_async_commit();
        }

        ull hv[16];
        const float* hp = &h_s[p][r][kh * 32];
#pragma unroll
        for (int q = 0; q < 8; q++) {
            ulonglong2 v = *(const ulonglong2*)(hp + q * 4);
            hv[q * 2] = v.x; hv[q * 2 + 1] = v.y;
        }

        ull ae[4] = {0ull, 0ull, 0ull, 0ull};
        ull ao[4] = {0ull, 0ull, 0ull, 0ull};
#pragma unroll
        for (int kp = 0; kp < 16; kp += 2) {
#pragma unroll
            for (int g = 0; g < 4; g++) {
                fma2(ae[g], w2[g * 16 + kp], hv[kp]);
                fma2(ao[g], w2[g * 16 + kp + 1], hv[kp + 1]);
            }
        }
        float s[4];
#pragma unroll
        for (int g = 0; g < 4; g++) {
            float2 f = unpack2(add2(ae[g], ao[g]));
            s[g] = f.x + f.y;
            s[g] += __shfl_xor_sync(0xffffffffu, s[g], 16);
        }

        float zi, zf, zg, zo;
        if (constProj) {
            zi = s[0] + gc[0]; zf = s[1] + gc[1]; zg = s[2] + gc[2]; zo = s[3] + gc[3];
        } else {
            zi = s[0] + gbuf[st][r][j];
            zf = s[1] + gbuf[st][r][64 + j];
            zg = s[2] + gbuf[st][r][128 + j];
            zo = s[3] + gbuf[st][r][192 + j];
        }
        c = fsig(zf) * c + fsig(zi) * fmaxf(zg, 0.f);
        hcur = fsig(zo) * fmaxf(c, 0.f);
        if (kh == 0) h_s[p ^ 1][r][j] = hcur;
        else if (hseq) hseq[((size_t)(b0 + r) * TT + t) * 64 + j] = hcur;

        if (!constProj) cp_async_wait6();
        __syncthreads();
        p ^= 1;
    }
    if (hlast && kh == 0)
        hlast[(size_t)(b0 + r) * 64 + j] = hcur;
}

// ---------------- LSTM recurrence, H=128; 512 threads, 2-way k-split --------
// Dynamic smem layout (floats):
//   h_s   [2][4][128]  : offset 0      (1024 f)
//   z_s   [4][256]     : offset 1024   (1024 f)
//   gbuf  [8][4][256]  : offset 2048   (8192 f)
//   wo2   [64][32] ull : offset 10240  (4096 f)
//   bo_s  [32]         : offset 14336  (32 f)
//   mbar  ull          : offset 14368  (2 f)
// total 14370 f = 57480 B -> request 57600
__global__ void __launch_bounds__(512) __cluster_dims__(2, 1, 1)
lstm128_kernel(const float* __restrict__ gproj, // [BT,512]
               const float* __restrict__ Wr,    // [128,512]
               float* __restrict__ hseq,        // [BT,128] or null
               const float* __restrict__ Wout,  // [128,64] or null (fused out)
               const float* __restrict__ bout,  // [64]
               float* __restrict__ outp) {      // [BT,64]
    extern __shared__ __align__(16) float sm[];
    float (*h_s)[4][128] = (float (*)[4][128])sm;            // [2][4][128]
    float (*z_s)[256]    = (float (*)[256])(sm + 1024);      // [4][256]
    float (*gbuf)[4][256] = (float (*)[4][256])(sm + 2048);  // [8][4][256]
    ull (*wo2)[32]       = (ull (*)[32])(sm + 10240);        // [64][32]
    float* bo_s          = sm + 14336;                       // [32]
    ull* mbar_p          = (ull*)(sm + 14368);

    const int tid = threadIdx.x;
    uint32_t q;
    asm("mov.u32 %0, %%cluster_ctarank;" : "=r"(q));
    const uint32_t peer = q ^ 1u;
    const int b0 = (blockIdx.x >> 1) * 4;

    const int lane = tid & 31, warp = tid >> 5;
    const int kh = lane >> 4;                       // k half: [kh*64, kh*64+64)
    const int col = (lane & 15) + (warp << 4);      // local gate col 0..255
    const int gc = (col >> 6) * 128 + (int)q * 64 + (col & 63);

    // weights: 32 k-pairs of this thread's half for its gate column
    ull w2[32];
#pragma unroll
    for (int kp = 0; kp < 32; kp++) {
        int k = kh * 64 + 2 * kp;
        w2[kp] = pack2(Wr[(size_t)k * 512 + gc], Wr[(size_t)(k + 1) * 512 + gc]);
    }

    // fused-out weights: wo2[k2][oc] = (Wout[2k2][q*32+oc], Wout[2k2+1][q*32+oc])
    if (Wout) {
        for (int i = tid; i < 2048; i += 512) {
            int k2 = i >> 5, oc = i & 31;
            wo2[k2][oc] = pack2(Wout[(size_t)(2 * k2) * 64 + (int)q * 32 + oc],
                                Wout[(size_t)(2 * k2 + 1) * 64 + (int)q * 32 + oc]);
        }
        if (tid < 32) bo_s[tid] = bout[(int)q * 32 + tid];
    }

    if (tid < 512) h_s[0][tid >> 7][tid & 127] = 0.f;
    const uint32_t mbar = (uint32_t)__cvta_generic_to_shared(mbar_p);
    if (tid == 0)
        asm volatile("mbarrier.init.shared.b64 [%0], %1;\n" :: "r"(mbar), "r"(8u) : "memory");
    __syncthreads();

    // gbuf prefetch (threads 0..255): local col n holds global gate col map
    const int pr = (tid >> 6) & 3, c4 = (tid & 63) * 4;
    const int pcol = (c4 >> 6) * 128 + (int)q * 64 + (c4 & 63);
    for (int s = 0; s < 7; s++) {
        if (tid < 256)
            cp_async16(&gbuf[s][pr][c4], gproj + ((size_t)(b0 + pr) * TT + s) * 512 + pcol);
        cp_async_commit();
    }
    cp_async_wait6();
    __syncthreads();
    cluster_sync_();   // mbar + h buffers visible cluster-wide

    const int r2 = (tid >> 6) & 3, jj = tid & 63;   // phase-2 mapping (tid<256)
    const int jg = (int)q * 64 + jj;
    const int orow = (tid - 256) >> 5, oc = tid & 31;  // fused-out map (256<=tid<384)
    float c = 0.f;
    int p = 0;
    uint32_t par = 0;

    for (int t = 0; t < TT; t++) {
        const int st = t & 7;
        if (tid < 256 && t + 7 < TT)
            cp_async16(&gbuf[(t + 7) & 7][pr][c4],
                       gproj + ((size_t)(b0 + pr) * TT + t + 7) * 512 + pcol);
        cp_async_commit();

        // phase 1: partial dots for 4 rows over this thread's 64-k half
        ull a[4] = {0ull, 0ull, 0ull, 0ull};
        ull e[4] = {0ull, 0ull, 0ull, 0ull};
        const ull* h0 = (const ull*)&h_s[p][0][kh * 64];
        const ull* h1 = (const ull*)&h_s[p][1][kh * 64];
        const ull* h2 = (const ull*)&h_s[p][2][kh * 64];
        const ull* h3 = (const ull*)&h_s[p][3][kh * 64];
#pragma unroll
        for (int kp = 0; kp < 32; kp += 2) {
            ulonglong2 u0 = *(const ulonglong2*)&h0[kp];
            ulonglong2 u1 = *(const ulonglong2*)&h1[kp];
            ulonglong2 u2 = *(const ulonglong2*)&h2[kp];
            ulonglong2 u3 = *(const ulonglong2*)&h3[kp];
            fma2(a[0], w2[kp], u0.x); fma2(e[0], w2[kp + 1], u0.y);
            fma2(a[1], w2[kp], u1.x); fma2(e[1], w2[kp + 1], u1.y);
            fma2(a[2], w2[kp], u2.x); fma2(e[2], w2[kp + 1], u2.y);
            fma2(a[3], w2[kp], u3.x); fma2(e[3], w2[kp + 1], u3.y);
        }
#pragma unroll
        for (int r = 0; r < 4; r++) {
            float2 f = unpack2(add2(a[r], e[r]));
            float s = f.x + f.y;
            s += __shfl_xor_sync(0xffffffffu, s, 16);   // combine k halves
            if (kh == 0) z_s[r][col] = s + gbuf[st][r][col];
        }
        __syncthreads();

        // phase 2a: warps 0-7 — gates for (row r2, local col jj)
        if (tid < 256) {
            float zi = z_s[r2][jj];
            float zf = z_s[r2][64 + jj];
            float zg = z_s[r2][128 + jj];
            float zo = z_s[r2][192 + jj];
            c = fsig(zf) * c + fsig(zi) * fmaxf(zg, 0.f);
            float h = fsig(zo) * fmaxf(c, 0.f);
            float* own = &h_s[p ^ 1][r2][jg];
            *own = h;
            st_remote_f32(own, peer, h);
            if (hseq) hseq[((size_t)(b0 + r2) * TT + t) * 128 + jg] = h;
            __syncwarp();
            if (lane == 0) mbar_arrive_remote(mbar, peer);
        }
        // phase 2b: warps 8-11 — fused out(t-1) = h(t-1) @ Wout + bout
        else if (tid < 384 && Wout && t > 0) {
            const ull* hp = (const ull*)&h_s[p][orow][0];   // h(t-1), stable
            ull oa = 0ull, ob = 0ull;
#pragma unroll
            for (int k2 = 0; k2 < 64; k2 += 2) {
                ulonglong2 hv = *(const ulonglong2*)&hp[k2];
                fma2(oa, wo2[k2][oc], hv.x);
                fma2(ob, wo2[k2 + 1][oc], hv.y);
            }
            float2 f = unpack2(add2(oa, ob));
            outp[((size_t)(b0 + orow) * TT + (t - 1)) * 64 + (int)q * 32 + oc] =
                f.x + f.y + bo_s[oc];
        }

        cp_async_wait6();
        __syncthreads();       // local h half + z_s/gbuf reuse ordering
        mbar_wait(mbar, par);  // acquire peer's 8 arrivals
        par ^= 1;
        p ^= 1;
    }

    // final fused out(TT-1) from h_s[p] (= h(TT-1), complete after mbar_wait)
    if (Wout && tid >= 256 && tid < 384) {
        const ull* hp = (const ull*)&h_s[p][orow][0];
        ull oa = 0ull, ob = 0ull;
#pragma unroll
        for (int k2 = 0; k2 < 64; k2 += 2) {
            ulonglong2 hv = *(const ulonglong2*)&hp[k2];
            fma2(oa, wo2[k2][oc], hv.x);
            fma2(ob, wo2[k2 + 1][oc], hv.y);
        }
        float2 f = unpack2(add2(oa, ob));
        outp[((size_t)(b0 + orow) * TT + (TT - 1)) * 64 + (int)q * 32 + oc] =
            f.x + f.y + bo_s[oc];
    }
}

// ---------------- host orchestration ----------------------------------------
extern "C" void kernel_launch(void* const* d_in, const int* in_sizes, int n_in,
                              void* d_out, int out_size) {
    const float* x    = (const float*)d_in[0];
    const float* Wk1  = (const float*)d_in[1];
    const float* Wr1  = (const float*)d_in[2];
    const float* b1   = (const float*)d_in[3];
    const float* Wk2  = (const float*)d_in[4];
    const float* Wr2  = (const float*)d_in[5];
    const float* b2   = (const float*)d_in[6];
    const float* Wd1k = (const float*)d_in[7];
    const float* Wd1r = (const float*)d_in[8];
    const float* bd1  = (const float*)d_in[9];
    const float* Wd2k = (const float*)d_in[10];
    const float* Wd2r = (const float*)d_in[11];
    const float* bd2  = (const float*)d_in[12];
    const float* Wout = (const float*)d_in[13];
    const float* bout = (const float*)d_in[14];
    float* out = (float*)d_out;

    float *bufG, *h1, *d1, *z, *gd1;
    cudaGetSymbolAddress((void**)&bufG, g_bufG);
    cudaGetSymbolAddress((void**)&h1,  g_h1);
    cudaGetSymbolAddress((void**)&d1,  g_d1);
    cudaGetSymbolAddress((void**)&z,   g_z);
    cudaGetSymbolAddress((void**)&gd1, g_gd1);

    const int SMEM_L128 = 57600;
    cudaFuncSetAttribute(lstm128_kernel, cudaFuncAttributeMaxDynamicSharedMemorySize, SMEM_L128);

    dim3 blk(256);
    dim3 blkL(512);

    // 1) G1 = x @ Wk1 + b1                     [BT,512]
    gemm_f32x2_kernel<<<dim3(1024, 4), blk>>>(x, Wk1, b1, bufG, BT, 512, 64);
    // 2) encoder L1 recurrence -> h1           [BT,128]
    lstm128_kernel<<<128, blkL, SMEM_L128>>>(bufG, Wr1, h1, nullptr, nullptr, nullptr);
    // 3) G2 = h1 @ Wk2 + b2                    [BT,256]
    gemm_f32x2_kernel<<<dim3(1024, 2), blk>>>(h1, Wk2, b2, bufG, BT, 256, 128);
    // 4) encoder L2 recurrence -> z (last h)   [256,64]
    lstm64_kernel<<<128, blk>>>(bufG, Wr2, nullptr, z, 0);
    // 5) Gd1 = z @ Wd1k + bd1 (constant/step)  [256,256]
    gemm_f32x2_kernel<<<dim3(2, 2), blk>>>(z, Wd1k, bd1, gd1, 256, 256, 64);
    // 6) decoder L1 recurrence -> d1           [BT,64]
    lstm64_kernel<<<128, blk>>>(gd1, Wd1r, d1, nullptr, 1);
    // 7) Gd2 = d1 @ Wd2k + bd2                 [BT,512]
    gemm_f32x2_kernel<<<dim3(1024, 4), blk>>>(d1, Wd2k, bd2, bufG, BT, 512, 64);
    // 8) decoder L2 recurrence + FUSED final dense -> out  [BT,64]
    lstm128_kernel<<<128, blkL, SMEM_L128>>>(bufG, Wd2r, nullptr, Wout, bout, out);
}

// round 9
// speedup vs baseline: 1.4545x; 1.0379x over previous
#include <cuda_runtime.h>
#include <cstdint>

#define BT 131072   // B*T = 256*512
#define TT 512

typedef unsigned long long ull;

// ---------------- scratch (device globals; no runtime allocation) ----------
__device__ float g_bufG[67108864];  // [BT,512]  G1 / G2 / Gd2 (reused)
__device__ float g_h1[16777216];    // [BT,128]
__device__ float g_d1[8388608];     // [BT,64]
__device__ float g_z[16384];        // [256,64]
__device__ float g_gd1[65536];      // [256,256]

// ---------------- packed f32x2 helpers --------------------------------------
__device__ __forceinline__ ull dup2(float x) {
    ull r; asm("mov.b64 %0, {%1, %1};" : "=l"(r) : "f"(x)); return r;
}
__device__ __forceinline__ ull pack2(float lo, float hi) {
    ull r; asm("mov.b64 %0, {%1, %2};" : "=l"(r) : "f"(lo), "f"(hi)); return r;
}
__device__ __forceinline__ float2 unpack2(ull v) {
    float2 f; asm("mov.b64 {%0, %1}, %2;" : "=f"(f.x), "=f"(f.y) : "l"(v)); return f;
}
__device__ __forceinline__ void fma2(ull& acc, ull a, ull b) {
    asm("fma.rn.f32x2 %0, %1, %2, %0;" : "+l"(acc) : "l"(a), "l"(b));
}
__device__ __forceinline__ ull add2(ull a, ull b) {
    ull d; asm("add.rn.f32x2 %0, %1, %2;" : "=l"(d) : "l"(a), "l"(b)); return d;
}

// fast sigmoid: 1/(1 + 2^(-x*log2e)) via ex2.approx + rcp.approx (~1e-6 rel)
__device__ __forceinline__ float fsig(float x) {
    float r;
    asm("{\n\t.reg .f32 t;\n\t"
        "mul.f32 t, %1, 0fBFB8AA3B;\n\t"
        "ex2.approx.f32 t, t;\n\t"
        "add.f32 t, t, 0f3F800000;\n\t"
        "rcp.approx.f32 %0, t;\n\t}"
        : "=f"(r) : "f"(x));
    return r;
}

// ---------------- misc helpers ----------------------------------------------
__device__ __forceinline__ void cp_async16(void* smem_dst, const void* gmem_src) {
    uint32_t s = (uint32_t)__cvta_generic_to_shared(smem_dst);
    asm volatile("cp.async.cg.shared.global [%0], [%1], 16;\n" :: "r"(s), "l"(gmem_src));
}
__device__ __forceinline__ void cp_async_commit() { asm volatile("cp.async.commit_group;\n"); }
__device__ __forceinline__ void cp_async_wait6()  { asm volatile("cp.async.wait_group 6;\n"); }
__device__ __forceinline__ void cp_async_wait0()  { asm volatile("cp.async.wait_group 0;\n"); }

__device__ __forceinline__ void cluster_sync_() {
    asm volatile("barrier.cluster.arrive.aligned;\n" ::: "memory");
    asm volatile("barrier.cluster.wait.aligned;\n" ::: "memory");
}
__device__ __forceinline__ void st_remote_f32(float* local_ptr, uint32_t peer, float v) {
    uint32_t la = (uint32_t)__cvta_generic_to_shared(local_ptr);
    uint32_t ra;
    asm("mapa.shared::cluster.u32 %0, %1, %2;\n" : "=r"(ra) : "r"(la), "r"(peer));
    asm volatile("st.shared::cluster.f32 [%0], %1;\n" :: "r"(ra), "f"(v) : "memory");
}
__device__ __forceinline__ void mbar_arrive_remote(uint32_t local_mbar, uint32_t peer) {
    uint32_t ra;
    asm("mapa.shared::cluster.u32 %0, %1, %2;\n" : "=r"(ra) : "r"(local_mbar), "r"(peer));
    asm volatile("mbarrier.arrive.release.cluster.shared::cluster.b64 _, [%0];\n"
                 :: "r"(ra) : "memory");
}
__device__ __forceinline__ void mbar_wait(uint32_t mbar, uint32_t parity) {
    asm volatile(
        "{\n\t.reg .pred P;\n"
        "WAITL_%=:\n\t"
        "mbarrier.try_wait.parity.acquire.cluster.shared::cta.b64 P, [%0], %1, 0x989680;\n\t"
        "@!P bra WAITL_%=;\n"
        "}" :: "r"(mbar), "r"(parity) : "memory");
}

// ---------------- bulk GEMM: C[M,N] = A[M,K] @ W[K,N] + bias ----------------
// 128x128 tile, BK=16, 256 threads, f32x2 accumulation. (R3 proven version)
__global__ void __launch_bounds__(256)
gemm_f32x2_kernel(const float* __restrict__ A,
                  const float* __restrict__ W,
                  const float* __restrict__ bias,
                  float* __restrict__ C,
                  int M, int N, int K) {
    constexpr int BN = 128;
    __shared__ __align__(16) float As[2][16][128];
    __shared__ __align__(16) float Bs[2][16][BN];
    const int tid = threadIdx.x;
    const int m0 = blockIdx.x * 128, n0 = blockIdx.y * BN;
    const int tx = tid & 15, ty = tid >> 4;

    const int am = tid >> 1, ak = (tid & 1) * 8;
    const int nper = (16 * BN / 4) / 256;   // 2

    ull acc[8][4];
#pragma unroll
    for (int i = 0; i < 8; i++)
#pragma unroll
        for (int j = 0; j < 4; j++) acc[i][j] = 0ull;

    const int nk = K / 16;

    {
        const float* ap = A + (size_t)(m0 + am) * K + ak;
        float4 va = *(const float4*)ap;
        float4 vb = *(const float4*)(ap + 4);
#pragma unroll
        for (int q = 0; q < nper; q++) {
            int idx = tid * nper + q;
            int br = idx / (BN / 4), bc = (idx % (BN / 4)) * 4;
            cp_async16(&Bs[0][br][bc], W + (size_t)br * N + n0 + bc);
        }
        cp_async_commit();
        As[0][ak + 0][am] = va.x; As[0][ak + 1][am] = va.y;
        As[0][ak + 2][am] = va.z; As[0][ak + 3][am] = va.w;
        As[0][ak + 4][am] = vb.x; As[0][ak + 5][am] = vb.y;
        As[0][ak + 6][am] = vb.z; As[0][ak + 7][am] = vb.w;
        cp_async_wait0();
        __syncthreads();
    }

    for (int kt = 0; kt < nk; kt++) {
        const int p = kt & 1;
        const bool more = (kt + 1) < nk;
        float4 va, vb;
        if (more) {
            const float* ap = A + (size_t)(m0 + am) * K + (kt + 1) * 16 + ak;
            va = *(const float4*)ap;
            vb = *(const float4*)(ap + 4);
#pragma unroll
            for (int q = 0; q < nper; q++) {
                int idx = tid * nper + q;
                int br = idx / (BN / 4), bc = (idx % (BN / 4)) * 4;
                cp_async16(&Bs[p ^ 1][br][bc], W + (size_t)((kt + 1) * 16 + br) * N + n0 + bc);
            }
        }
        cp_async_commit();

#pragma unroll
        for (int k = 0; k < 16; k++) {
            float4 a0 = *(const float4*)&As[p][k][ty * 4];
            float4 a1 = *(const float4*)&As[p][k][64 + ty * 4];
            ulonglong2 b0v = *(const ulonglong2*)&Bs[p][k][tx * 4];
            ulonglong2 b1v = *(const ulonglong2*)&Bs[p][k][64 + tx * 4];
            float av[8] = {a0.x, a0.y, a0.z, a0.w, a1.x, a1.y, a1.z, a1.w};
#pragma unroll
            for (int i = 0; i < 8; i++) {
                ull aa = dup2(av[i]);
                fma2(acc[i][0], aa, b0v.x);
                fma2(acc[i][1], aa, b0v.y);
                fma2(acc[i][2], aa, b1v.x);
                fma2(acc[i][3], aa, b1v.y);
            }
        }

        if (more) {
            As[p ^ 1][ak + 0][am] = va.x; As[p ^ 1][ak + 1][am] = va.y;
            As[p ^ 1][ak + 2][am] = va.z; As[p ^ 1][ak + 3][am] = va.w;
            As[p ^ 1][ak + 4][am] = vb.x; As[p ^ 1][ak + 5][am] = vb.y;
            As[p ^ 1][ak + 6][am] = vb.z; As[p ^ 1][ak + 7][am] = vb.w;
        }
        cp_async_wait0();
        __syncthreads();
    }

    ull bz[4];
    bz[0] = *(const ull*)&bias[n0 + tx * 4];
    bz[1] = *(const ull*)&bias[n0 + tx * 4 + 2];
    bz[2] = *(const ull*)&bias[n0 + 64 + tx * 4];
    bz[3] = *(const ull*)&bias[n0 + 64 + tx * 4 + 2];
#pragma unroll
    for (int i = 0; i < 8; i++) {
        int row = m0 + ((i < 4) ? (ty * 4 + i) : (64 + ty * 4 + i - 4));
        ulonglong2 o0;
        o0.x = add2(acc[i][0], bz[0]);
        o0.y = add2(acc[i][1], bz[1]);
        *(ulonglong2*)&C[(size_t)row * N + n0 + tx * 4] = o0;
        ulonglong2 o1;
        o1.x = add2(acc[i][2], bz[2]);
        o1.y = add2(acc[i][3], bz[3]);
        *(ulonglong2*)&C[(size_t)row * N + n0 + 64 + tx * 4] = o1;
    }
}

// ---------------- LSTM recurrence, H=64 (R4 version; measured ~265us) -------
__global__ void __launch_bounds__(256)
lstm64_kernel(const float* __restrict__ gproj, // [BT,256] or [256,256] if constProj
              const float* __restrict__ Wr,    // [64,256]
              float* __restrict__ hseq,        // [BT,64] or null
              float* __restrict__ hlast,       // [256,64] or null
              int constProj) {
    __shared__ __align__(16) float h_s[2][2][64];
    __shared__ __align__(16) float gbuf[8][2][256];   // 16KB

    const int tid = threadIdx.x;
    const int b0 = blockIdx.x * 2;
    const int w = tid >> 5, lane = tid & 31;
    const int r = w >> 2;                    // row 0/1
    const int j = (w & 3) * 16 + (lane & 15);
    const int kh = lane >> 4;                // k half: k in [kh*32, kh*32+32)

    ull w2[64];
#pragma unroll
    for (int g = 0; g < 4; g++)
#pragma unroll
        for (int kp = 0; kp < 16; kp++) {
            int k = kh * 32 + 2 * kp;
            w2[g * 16 + kp] = pack2(Wr[k * 256 + g * 64 + j],
                                    Wr[(k + 1) * 256 + g * 64 + j]);
        }

    if (tid < 128) h_s[0][tid >> 6][tid & 63] = 0.f;

    const int pr = tid >> 6, c4 = (tid & 63) * 4;
    float gc[4] = {0.f, 0.f, 0.f, 0.f};
    if (constProj) {
#pragma unroll
        for (int g = 0; g < 4; g++)
            gc[g] = gproj[(size_t)(b0 + r) * 256 + g * 64 + j];
    } else {
        for (int s = 0; s < 7; s++) {
            if (tid < 128)
                cp_async16(&gbuf[s][pr][c4], gproj + ((size_t)(b0 + pr) * TT + s) * 256 + c4);
            cp_async_commit();
        }
        cp_async_wait6();
    }
    __syncthreads();

    float c = 0.f;
    float hcur = 0.f;
    int p = 0;

    for (int t = 0; t < TT; t++) {
        const int st = t & 7;
        if (!constProj) {
            if (tid < 128 && t + 7 < TT)
                cp_async16(&gbuf[(t + 7) & 7][pr][c4],
                           gproj + ((size_t)(b0 + pr) * TT + t + 7) * 256 + c4);
            cp_async_commit();
        }

        ull hv[16];
        const float* hp = &h_s[p][r][kh * 32];
#pragma unroll
        for (int q = 0; q < 8; q++) {
            ulonglong2 v = *(const ulonglong2*)(hp + q * 4);
            hv[q * 2] = v.x; hv[q * 2 + 1] = v.y;
        }

        ull ae[4] = {0ull, 0ull, 0ull, 0ull};
        ull ao[4] = {0ull, 0ull, 0ull, 0ull};
#pragma unroll
        for (int kp = 0; kp < 16; kp += 2) {
#pragma unroll
            for (int g = 0; g < 4; g++) {
                fma2(ae[g], w2[g * 16 + kp], hv[kp]);
                fma2(ao[g], w2[g * 16 + kp + 1], hv[kp + 1]);
            }
        }
        float s[4];
#pragma unroll
        for (int g = 0; g < 4; g++) {
            float2 f = unpack2(add2(ae[g], ao[g]));
            s[g] = f.x + f.y;
            s[g] += __shfl_xor_sync(0xffffffffu, s[g], 16);
        }

        float zi, zf, zg, zo;
        if (constProj) {
            zi = s[0] + gc[0]; zf = s[1] + gc[1]; zg = s[2] + gc[2]; zo = s[3] + gc[3];
        } else {
            zi = s[0] + gbuf[st][r][j];
            zf = s[1] + gbuf[st][r][64 + j];
            zg = s[2] + gbuf[st][r][128 + j];
            zo = s[3] + gbuf[st][r][192 + j];
        }
        c = fsig(zf) * c + fsig(zi) * fmaxf(zg, 0.f);
        hcur = fsig(zo) * fmaxf(c, 0.f);
        if (kh == 0) h_s[p ^ 1][r][j] = hcur;
        else if (hseq) hseq[((size_t)(b0 + r) * TT + t) * 64 + j] = hcur;

        if (!constProj) cp_async_wait6();
        __syncthreads();
        p ^= 1;
    }
    if (hlast && kh == 0)
        hlast[(size_t)(b0 + r) * 64 + j] = hcur;
}

// ---------------- LSTM recurrence, H=128 (R3 256-thr core + fused out) ------
// 2-CTA cluster, 64 clusters, 4 batch rows per CTA. Threads 0-255: exact R3
// structure (thread = gate-col, 4 rows, z_s roundtrip). Optional extra warps
// (launch 384 threads when Wout != null): threads 256-383 are barrier-only in
// phase 1 and compute the fused out(t-1) = h(t-1) @ Wout + bout in phase 2
// (1 output col each; this CTA covers its 32-col half, peer covers the rest).
// Dynamic smem (floats): h_s 1024 | z_s 1024 | gbuf 8192 | wo2 4096 | bo 32 | mbar 2
__global__ void __launch_bounds__(384) __cluster_dims__(2, 1, 1)
lstm128_kernel(const float* __restrict__ gproj, // [BT,512]
               const float* __restrict__ Wr,    // [128,512]
               float* __restrict__ hseq,        // [BT,128] or null
               const float* __restrict__ Wout,  // [128,64] or null (fused out)
               const float* __restrict__ bout,  // [64]
               float* __restrict__ outp) {      // [BT,64]
    extern __shared__ __align__(16) float sm[];
    float (*h_s)[4][128]  = (float (*)[4][128])sm;           // [2][4][128]
    float (*z_s)[256]     = (float (*)[256])(sm + 1024);     // [4][256]
    float (*gbuf)[4][256] = (float (*)[4][256])(sm + 2048);  // [8][4][256]
    ull (*wo2)[32]        = (ull (*)[32])(sm + 10240);       // [64][32]
    float* bo_s           = sm + 14336;                      // [32]
    ull* mbar_p           = (ull*)(sm + 14368);

    const int tid = threadIdx.x;
    const int nthr = blockDim.x;
    uint32_t q;
    asm("mov.u32 %0, %%cluster_ctarank;" : "=r"(q));
    const uint32_t peer = q ^ 1u;
    const int b0 = (blockIdx.x >> 1) * 4;
    const int gcol = ((tid >> 6) & 3) * 128 + (int)q * 64 + (tid & 63);

    // compute-warp weights (threads 0-255 use them; others load junk-free 0s)
    ull w2[64];
    if (tid < 256) {
#pragma unroll
        for (int kp = 0; kp < 64; kp++)
            w2[kp] = pack2(Wr[(size_t)(2 * kp) * 512 + gcol],
                           Wr[(size_t)(2 * kp + 1) * 512 + gcol]);
    }

    // fused-out weights into smem
    if (Wout) {
        for (int i = tid; i < 2048; i += nthr) {
            int k2 = i >> 5, oc = i & 31;
            wo2[k2][oc] = pack2(Wout[(size_t)(2 * k2) * 64 + (int)q * 32 + oc],
                                Wout[(size_t)(2 * k2 + 1) * 64 + (int)q * 32 + oc]);
        }
        if (tid < 32) bo_s[tid] = bout[(int)q * 32 + tid];
    }

    for (int i = tid; i < 512; i += nthr) h_s[0][i >> 7][i & 127] = 0.f;
    const uint32_t mbar = (uint32_t)__cvta_generic_to_shared(mbar_p);
    if (tid == 0)
        asm volatile("mbarrier.init.shared.b64 [%0], %1;\n" :: "r"(mbar), "r"(8u) : "memory");
    __syncthreads();

    const int pr = (tid >> 6) & 3, c4 = (tid & 63) * 4;
    const int pcol = (c4 >> 6) * 128 + (int)q * 64 + (c4 & 63);
    for (int s = 0; s < 7; s++) {
        if (tid < 256)
            cp_async16(&gbuf[s][pr][c4], gproj + ((size_t)(b0 + pr) * TT + s) * 512 + pcol);
        cp_async_commit();
    }
    cp_async_wait6();
    __syncthreads();
    cluster_sync_();

    const int r2 = (tid >> 6) & 3, jj = tid & 63;
    const int jg = (int)q * 64 + jj;
    const int lane = tid & 31;
    const int orow = (tid - 256) >> 5, oc = tid & 31;   // fused-out map (tid>=256)
    float c = 0.f;
    int p = 0;
    uint32_t par = 0;

    for (int t = 0; t < TT; t++) {
        const int st = t & 7;
        if (tid < 256 && t + 7 < TT)
            cp_async16(&gbuf[(t + 7) & 7][pr][c4],
                       gproj + ((size_t)(b0 + pr) * TT + t + 7) * 512 + pcol);
        cp_async_commit();

        if (tid < 256) {
            // phase 1 (R3): z for gate col tid, 4 rows
            ull a[4], e[4];
#pragma unroll
            for (int r = 0; r < 4; r++) { a[r] = 0ull; e[r] = 0ull; }
            const float* h0p = h_s[p][0];
            const float* h1p = h_s[p][1];
            const float* h2p = h_s[p][2];
            const float* h3p = h_s[p][3];
#pragma unroll
            for (int kp = 0; kp < 64; kp += 2) {
                ulonglong2 u0 = *(const ulonglong2*)(h0p + 2 * kp);
                ulonglong2 u1 = *(const ulonglong2*)(h1p + 2 * kp);
                ulonglong2 u2 = *(const ulonglong2*)(h2p + 2 * kp);
                ulonglong2 u3 = *(const ulonglong2*)(h3p + 2 * kp);
                fma2(a[0], w2[kp], u0.x); fma2(e[0], w2[kp + 1], u0.y);
                fma2(a[1], w2[kp], u1.x); fma2(e[1], w2[kp + 1], u1.y);
                fma2(a[2], w2[kp], u2.x); fma2(e[2], w2[kp + 1], u2.y);
                fma2(a[3], w2[kp], u3.x); fma2(e[3], w2[kp + 1], u3.y);
            }
#pragma unroll
            for (int r = 0; r < 4; r++) {
                float2 f = unpack2(add2(a[r], e[r]));
                z_s[r][tid] = gbuf[st][r][tid] + (f.x + f.y);
            }
        }
        __syncthreads();

        // phase 2a: threads 0-255 — gates for (row r2, local col jj)
        if (tid < 256) {
            float zi = z_s[r2][jj];
            float zf = z_s[r2][64 + jj];
            float zg = z_s[r2][128 + jj];
            float zo = z_s[r2][192 + jj];
            c = fsig(zf) * c + fsig(zi) * fmaxf(zg, 0.f);
            float h = fsig(zo) * fmaxf(c, 0.f);
            float* own = &h_s[p ^ 1][r2][jg];
            *own = h;
            st_remote_f32(own, peer, h);
            if (hseq) hseq[((size_t)(b0 + r2) * TT + t) * 128 + jg] = h;
            __syncwarp();
            if (lane == 0) mbar_arrive_remote(mbar, peer);
        }
        // phase 2b: threads 256-383 — fused out(t-1) = h(t-1) @ Wout + bout
        else if (Wout && t > 0) {
            const ull* hp = (const ull*)&h_s[p][orow][0];   // h(t-1), stable
            ull oa = 0ull, ob = 0ull;
#pragma unroll
            for (int k2 = 0; k2 < 64; k2 += 2) {
                ulonglong2 hv = *(const ulonglong2*)&hp[k2];
                fma2(oa, wo2[k2][oc], hv.x);
                fma2(ob, wo2[k2 + 1][oc], hv.y);
            }
            float2 f = unpack2(add2(oa, ob));
            outp[((size_t)(b0 + orow) * TT + (t - 1)) * 64 + (int)q * 32 + oc] =
                f.x + f.y + bo_s[oc];
        }

        cp_async_wait6();
        __syncthreads();
        mbar_wait(mbar, par);
        par ^= 1;
        p ^= 1;
    }

    // final fused out(TT-1) from h_s[p] (complete after last mbar_wait)
    if (Wout && tid >= 256) {
        const ull* hp = (const ull*)&h_s[p][orow][0];
        ull oa = 0ull, ob = 0ull;
#pragma unroll
        for (int k2 = 0; k2 < 64; k2 += 2) {
            ulonglong2 hv = *(const ulonglong2*)&hp[k2];
            fma2(oa, wo2[k2][oc], hv.x);
            fma2(ob, wo2[k2 + 1][oc], hv.y);
        }
        float2 f = unpack2(add2(oa, ob));
        outp[((size_t)(b0 + orow) * TT + (TT - 1)) * 64 + (int)q * 32 + oc] =
            f.x + f.y + bo_s[oc];
    }
}

// ---------------- host orchestration ----------------------------------------
extern "C" void kernel_launch(void* const* d_in, const int* in_sizes, int n_in,
                              void* d_out, int out_size) {
    const float* x    = (const float*)d_in[0];
    const float* Wk1  = (const float*)d_in[1];
    const float* Wr1  = (const float*)d_in[2];
    const float* b1   = (const float*)d_in[3];
    const float* Wk2  = (const float*)d_in[4];
    const float* Wr2  = (const float*)d_in[5];
    const float* b2   = (const float*)d_in[6];
    const float* Wd1k = (const float*)d_in[7];
    const float* Wd1r = (const float*)d_in[8];
    const float* bd1  = (const float*)d_in[9];
    const float* Wd2k = (const float*)d_in[10];
    const float* Wd2r = (const float*)d_in[11];
    const float* bd2  = (const float*)d_in[12];
    const float* Wout = (const float*)d_in[13];
    const float* bout = (const float*)d_in[14];
    float* out = (float*)d_out;

    float *bufG, *h1, *d1, *z, *gd1;
    cudaGetSymbolAddress((void**)&bufG, g_bufG);
    cudaGetSymbolAddress((void**)&h1,  g_h1);
    cudaGetSymbolAddress((void**)&d1,  g_d1);
    cudaGetSymbolAddress((void**)&z,   g_z);
    cudaGetSymbolAddress((void**)&gd1, g_gd1);

    const int SMEM_L128 = 57600;
    cudaFuncSetAttribute(lstm128_kernel, cudaFuncAttributeMaxDynamicSharedMemorySize, SMEM_L128);

    dim3 blk(256);

    // 1) G1 = x @ Wk1 + b1                     [BT,512]
    gemm_f32x2_kernel<<<dim3(1024, 4), blk>>>(x, Wk1, b1, bufG, BT, 512, 64);
    // 2) encoder L1 recurrence -> h1           [BT,128]   (256 threads, no fusion)
    lstm128_kernel<<<128, 256, SMEM_L128>>>(bufG, Wr1, h1, nullptr, nullptr, nullptr);
    // 3) G2 = h1 @ Wk2 + b2                    [BT,256]
    gemm_f32x2_kernel<<<dim3(1024, 2), blk>>>(h1, Wk2, b2, bufG, BT, 256, 128);
    // 4) encoder L2 recurrence -> z (last h)   [256,64]
    lstm64_kernel<<<128, blk>>>(bufG, Wr2, nullptr, z, 0);
    // 5) Gd1 = z @ Wd1k + bd1 (constant/step)  [256,256]
    gemm_f32x2_kernel<<<dim3(2, 2), blk>>>(z, Wd1k, bd1, gd1, 256, 256, 64);
    // 6) decoder L1 recurrence -> d1           [BT,64]
    lstm64_kernel<<<128, blk>>>(gd1, Wd1r, d1, nullptr, 1);
    // 7) Gd2 = d1 @ Wd2k + bd2                 [BT,512]
    gemm_f32x2_kernel<<<dim3(1024, 4), blk>>>(d1, Wd2k, bd2, bufG, BT, 512, 64);
    // 8) decoder L2 recurrence + FUSED final dense -> out  [BT,64]  (384 threads)
    lstm128_kernel<<<128, 384, SMEM_L128>>>(bufG, Wd2r, nullptr, Wout, bout, out);
}